// round 1
// baseline (speedup 1.0000x reference)
#include <cuda_runtime.h>

#define N 128
#define BATCH 32
#define NITERS 500
#define RHO 0.1f
#define SIGMA 1e-6f
#define RELAX 1.6f
#define ALPHA 0.5f
#define DELTA 10.0f
#define NEGINF (-1e20f)

typedef unsigned long long ull;

// ---------------- device scratch (no allocations allowed) ----------------
__device__ float g_W[N * N];        // (2Q + 2*rho*J + (3*rho+sigma)I)^{-1}
__device__ float g_ypred[BATCH * N];

// ---------------- packed f32x2 helpers ----------------
__device__ __forceinline__ ull fma2(ull a, ull b, ull c) {
    ull d;
    asm("fma.rn.f32x2 %0, %1, %2, %3;" : "=l"(d) : "l"(a), "l"(b), "l"(c));
    return d;
}
__device__ __forceinline__ ull add2(ull a, ull b) {
    ull d;
    asm("add.rn.f32x2 %0, %1, %2;" : "=l"(d) : "l"(a), "l"(b));
    return d;
}
union F2U { ull u; float2 f; };

// ---------------- P0: y_pred = X @ beta ----------------
__global__ void ypred_kernel(const float* __restrict__ X,
                             const float* __restrict__ beta,
                             float* __restrict__ out) {
    __shared__ float xr[N];
    int b = blockIdx.x, j = threadIdx.x;
    xr[j] = X[b * N + j];
    __syncthreads();
    float acc = 0.f;
#pragma unroll 8
    for (int k = 0; k < N; k++) acc = fmaf(xr[k], beta[k * N + j], acc);
    g_ypred[b * N + j] = acc;
    out[BATCH * N + b * N + j] = acc;   // second half of output = y_pred
}

// ---------------- P1: build B and invert in shared (Gauss-Jordan) ----------------
// B = 2*(DELTA*V + (1-ALPHA)*gamma2*diag(d^2)) + 2*RHO*J + (3*RHO+SIGMA)*I
__global__ void build_invert_kernel(const float* __restrict__ V,
                                    const float* __restrict__ thD,
                                    const float* __restrict__ lg2) {
    extern __shared__ float Bs[];       // N x N with stride 129 (conflict-free cols)
    __shared__ float fbuf[N];
    __shared__ float dsh;
    const int tid = threadIdx.x;        // 256 threads
    float g2 = exp10f(lg2[0]);

    for (int idx = tid; idx < N * N; idx += 256) {
        int i = idx >> 7, jj = idx & 127;
        float v = 2.0f * DELTA * V[idx] + 2.0f * RHO;
        if (i == jj) {
            float dv = 1.0f / (1.0f + expf(-thD[i]));
            v += 2.0f * (1.0f - ALPHA) * g2 * dv * dv + 3.0f * RHO + SIGMA;
        }
        Bs[i * 129 + jj] = v;
    }
    __syncthreads();

    for (int k = 0; k < N; k++) {
        // phase 1: capture column k, scale row k
        if (tid < N) {
            float d = 1.0f / Bs[k * 129 + k];
            if (tid == 0) dsh = d;
            fbuf[tid] = Bs[tid * 129 + k];
            if (tid != k) Bs[k * 129 + tid] *= d;
        }
        __syncthreads();
        // phase 2: eliminate (each thread: one row-half)
        {
            int i = tid >> 1;
            int j0 = (tid & 1) * 64;
            if (i != k) {
                float f = fbuf[i];
#pragma unroll 8
                for (int j = j0; j < j0 + 64; j++) {
                    if (j != k) Bs[i * 129 + j] = fmaf(-f, Bs[k * 129 + j], Bs[i * 129 + j]);
                }
            }
        }
        __syncthreads();
        // phase 3: column k and pivot
        if (tid < N) {
            float d = dsh;
            if (tid != k) Bs[tid * 129 + k] = -fbuf[tid] * d;
            else          Bs[k * 129 + k] = d;
        }
        __syncthreads();
    }

    for (int idx = tid; idx < N * N; idx += 256)
        g_W[idx] = Bs[(idx >> 7) * 129 + (idx & 127)];
}

// ---------------- P2: persistent per-batch ADMM ----------------
// One CTA per batch item, 128 threads; thread j owns row j of W in registers
// (64 packed f32x2), plus state x1,x2 (x[j],x[128+j]), z/y rows (1+j),(129+j),(257+j),
// and a redundantly-tracked (z0,y0) identical across all threads.
__global__ void __launch_bounds__(128, 1)
solve_kernel(const float* __restrict__ thE, const float* __restrict__ lg1,
             const float* __restrict__ bvec, const float* __restrict__ hvec,
             float* __restrict__ out) {
    __shared__ __align__(16) float sdd[N];
    __shared__ float part[4];
    const int b = blockIdx.x, j = threadIdx.x;

    // W row -> registers as 64 f32x2 pairs
    ull w[64];
    {
        const float4* wr = reinterpret_cast<const float4*>(g_W + j * N);
#pragma unroll
        for (int k = 0; k < 32; k++) {
            float4 v = wr[k];
            F2U u0; u0.f = make_float2(v.x, v.y);
            F2U u1; u1.f = make_float2(v.z, v.w);
            w[2 * k] = u0.u;
            w[2 * k + 1] = u1.u;
        }
    }

    float g1v = exp10f(lg1[0]);
    float ev  = 1.0f / (1.0f + expf(-thE[j]));
    float pt  = ALPHA * g1v * ev;
    float yp  = g_ypred[b * N + j];
    const float p1 = -yp + pt, p2 = yp + pt;
    const float up1 = hvec[j];          // up[1+j] = h[j]
    const float b0  = bvec[0];          // lo[0]=up[0]=b
    const float inv_rs  = 1.0f / (RHO + SIGMA);
    const float inv_rho = 1.0f / RHO;
    const float omr = 1.0f - RELAX;

    float x1 = 0.f, x2 = 0.f;
    float z1 = 0.f, z2 = 0.f, z3 = 0.f;
    float y1 = 0.f, y2 = 0.f, y3 = 0.f;
    float z0 = 0.f, y0 = 0.f;           // tracked identically by all threads

    const ull* dds = reinterpret_cast<const ull*>(sdd);

    for (int it = 0; it < NITERS; it++) {
        // rhs = SIGMA*x - p + C^T(rho*z - y), exploiting C structure
        float w0 = RHO * z0 - y0;
        float wa = RHO * z1 - y1;
        float wb = RHO * z2 - y2;
        float wc = RHO * z3 - y3;
        float r1 = SIGMA * x1 - p1 + (w0 - wa - wb);
        float r2 = SIGMA * x2 - p2 + (wa - w0 - wc);
        float s  = r1 + r2;             // sum part  -> x1+x2 = s/(rho+sigma)
        sdd[j] = r1 - r2;               // diff part -> t = W (r1-r2)
        __syncthreads();

        // t_j = W[j,:] . dd  (registers x broadcast-shared, f32x2 FMA)
        ull a0 = 0ull, a1 = 0ull, a2 = 0ull, a3 = 0ull;
#pragma unroll
        for (int k = 0; k < 64; k += 4) {
            a0 = fma2(w[k],     dds[k],     a0);
            a1 = fma2(w[k + 1], dds[k + 1], a1);
            a2 = fma2(w[k + 2], dds[k + 2], a2);
            a3 = fma2(w[k + 3], dds[k + 3], a3);
        }
        F2U acc; acc.u = add2(add2(a0, a1), add2(a2, a3));
        float t = acc.f.x + acc.f.y;

        // zt0 = sum(t) (cross-warp deterministic reduction)
        float r = t;
#pragma unroll
        for (int m = 16; m; m >>= 1) r += __shfl_xor_sync(0xffffffffu, r, m);
        if ((j & 31) == 0) part[j >> 5] = r;
        __syncthreads();
        float zt0 = (part[0] + part[1]) + (part[2] + part[3]);

        float su  = s * inv_rs;
        float xt1 = 0.5f * (su + t);
        float xt2 = 0.5f * (su - t);
        x1 = RELAX * xt1 + omr * x1;
        x2 = RELAX * xt2 + omr * x2;

        // row 0 (equality): lo=up=b0
        float zr0 = RELAX * zt0 + omr * z0;
        float zn0 = fminf(fmaxf(zr0 + y0 * inv_rho, b0), b0);
        y0 += RHO * (zr0 - zn0); z0 = zn0;

        // row 1+j: zt = -t_j, up=h[j]
        float zr1 = RELAX * (-t) + omr * z1;
        float zn1 = fminf(fmaxf(zr1 + y1 * inv_rho, NEGINF), up1);
        y1 += RHO * (zr1 - zn1); z1 = zn1;

        // row 129+j: zt = -xt1, up=0
        float zr2 = RELAX * (-xt1) + omr * z2;
        float zn2 = fminf(fmaxf(zr2 + y2 * inv_rho, NEGINF), 0.0f);
        y2 += RHO * (zr2 - zn2); z2 = zn2;

        // row 257+j: zt = -xt2, up=0
        float zr3 = RELAX * (-xt2) + omr * z3;
        float zn3 = fminf(fmaxf(zr3 + y3 * inv_rho, NEGINF), 0.0f);
        y3 += RHO * (zr3 - zn3); z3 = zn3;
    }

    out[b * N + j] = x1 - x2;           // z_batch = u[:, :n] - u[:, n:]
}

// ---------------- launcher ----------------
extern "C" void kernel_launch(void* const* d_in, const int* in_sizes, int n_in,
                              void* d_out, int out_size) {
    const float* X    = (const float*)d_in[0];
    const float* V    = (const float*)d_in[1];
    const float* beta = (const float*)d_in[2];
    const float* thE  = (const float*)d_in[3];
    const float* thD  = (const float*)d_in[4];
    const float* lg1  = (const float*)d_in[5];
    const float* lg2  = (const float*)d_in[6];
    // d_in[7] = A (ones), d_in[9] = G (-I): structure exploited analytically
    const float* bvec = (const float*)d_in[8];
    const float* hvec = (const float*)d_in[10];
    float* out = (float*)d_out;

    const int inv_smem = N * 129 * (int)sizeof(float);  // 66048 B
    cudaFuncSetAttribute(build_invert_kernel,
                         cudaFuncAttributeMaxDynamicSharedMemorySize, inv_smem);

    ypred_kernel<<<BATCH, N>>>(X, beta, out);
    build_invert_kernel<<<1, 256, inv_smem>>>(V, thD, lg2);
    solve_kernel<<<BATCH, N>>>(thE, lg1, bvec, hvec, out);
}

// round 3
// speedup vs baseline: 1.5047x; 1.5047x over previous
#include <cuda_runtime.h>

#define N 128
#define BATCH 32
#define NITERS 500
#define RHO 0.1f
#define SIGMA 1e-6f
#define RELAX 1.6f
#define ALPHA 0.5f
#define DELTA 10.0f

typedef unsigned long long ull;

// ---------------- device scratch ----------------
__device__ float g_W[N * N];   // (2Q + 2*rho*J + (3*rho+sigma)I)^{-1}
__device__ float g_q[N];       // q = W @ 1  (row sums; W symmetric)
__device__ float g_Q1;         // 1^T W 1

// ---------------- packed f32x2 helpers ----------------
union F2U { ull u; float2 f; };
__device__ __forceinline__ ull pack2(float x, float y) { F2U u; u.f = make_float2(x, y); return u.u; }
__device__ __forceinline__ ull fma2(ull a, ull b, ull c) {
    ull d; asm("fma.rn.f32x2 %0, %1, %2, %3;" : "=l"(d) : "l"(a), "l"(b), "l"(c)); return d;
}
__device__ __forceinline__ ull add2(ull a, ull b) {
    ull d; asm("add.rn.f32x2 %0, %1, %2;" : "=l"(d) : "l"(a), "l"(b)); return d;
}
__device__ __forceinline__ ull mul2(ull a, ull b) {
    ull d; asm("mul.rn.f32x2 %0, %1, %2;" : "=l"(d) : "l"(a), "l"(b)); return d;
}

// ---------------- P1: register-resident Gauss-Jordan inversion ----------------
// B = 2*(DELTA*V + (1-ALPHA)*g2*diag(d^2)) + 2*RHO*J + (3*RHO+SIGMA)*I
// Thread i owns row i entirely in registers (64 f32x2). One barrier per pivot
// via double-buffered pivot-row export. Fully unrolled -> all static reg indices.
__global__ void __launch_bounds__(128, 1)
invert_kernel(const float* __restrict__ V, const float* __restrict__ thD,
              const float* __restrict__ lg2) {
    __shared__ __align__(16) ull rowbuf[2][64];
    __shared__ float red4[4];
    const int tid = threadIdx.x;

    const float g2 = exp10f(lg2[0]);
    const float sg = 1.0f / (1.0f + expf(-thD[tid]));
    const float dg = 2.0f * (1.0f - ALPHA) * g2 * sg * sg + 3.0f * RHO + SIGMA;

    ull rr[64];
    {
        const float2* vrow = reinterpret_cast<const float2*>(V + tid * N);
#pragma unroll
        for (int m = 0; m < 64; m++) {
            float2 v = vrow[m];
            float a = fmaf(2.0f * DELTA, v.x, 2.0f * RHO);
            float c = fmaf(2.0f * DELTA, v.y, 2.0f * RHO);
            if (2 * m == tid)     a += dg;
            if (2 * m + 1 == tid) c += dg;
            rr[m] = pack2(a, c);
        }
    }

#pragma unroll
    for (int k = 0; k < N; k++) {
        ull* buf = rowbuf[k & 1];
        if (tid == k) {
#pragma unroll
            for (int m = 0; m < 64; m++) buf[m] = rr[m];
        }
        __syncthreads();
        const float* bf = reinterpret_cast<const float*>(buf);
        const float d = 1.0f / bf[k];
        F2U fu; fu.u = rr[k >> 1];
        const float f = (k & 1) ? fu.f.y : fu.f.x;
        if (tid == k) {
            ull d2 = pack2(d, d);
#pragma unroll
            for (int m = 0; m < 64; m++) rr[m] = mul2(rr[m], d2);
            F2U t; t.u = rr[k >> 1];
            if (k & 1) t.f.y = d; else t.f.x = d;
            rr[k >> 1] = t.u;
        } else {
            float fd = f * d;
            ull nf2 = pack2(-fd, -fd);
#pragma unroll
            for (int m = 0; m < 64; m++) rr[m] = fma2(nf2, buf[m], rr[m]);
            F2U t; t.u = rr[k >> 1];
            if (k & 1) t.f.y = -fd; else t.f.x = -fd;
            rr[k >> 1] = t.u;
        }
    }

    // q = row sums, Q1 = total sum
    ull s0 = 0, s1 = 0, s2 = 0, s3 = 0;
#pragma unroll
    for (int m = 0; m < 64; m += 4) {
        s0 = add2(s0, rr[m]); s1 = add2(s1, rr[m + 1]);
        s2 = add2(s2, rr[m + 2]); s3 = add2(s3, rr[m + 3]);
    }
    F2U ts; ts.u = add2(add2(s0, s1), add2(s2, s3));
    float qs = ts.f.x + ts.f.y;
    g_q[tid] = qs;
    float r = qs;
#pragma unroll
    for (int m = 16; m; m >>= 1) r += __shfl_xor_sync(0xffffffffu, r, m);
    if ((tid & 31) == 0) red4[tid >> 5] = r;
    __syncthreads();
    if (tid == 0) g_Q1 = (red4[0] + red4[1]) + (red4[2] + red4[3]);

    ull* wout = reinterpret_cast<ull*>(g_W + tid * N);
#pragma unroll
    for (int m = 0; m < 64; m++) wout[m] = rr[m];
}

// ---------------- P2: persistent per-batch ADMM (256 threads, half-row split) ----------------
// thread tid -> row j = tid&127, half hf = tid>>7 (64 W-columns in registers).
// Scalar (z0,y0) decoupled via dd = dd_local + 2*w0*1:
//   t = W dd_local + 2*w0*q,  1^T t = q^T dd_local + 2*w0*Q1,
// so the cross-thread reduction (on q^T dd_local) starts BEFORE the matvec.
__global__ void __launch_bounds__(256, 1)
solve_kernel(const float* __restrict__ X, const float* __restrict__ beta,
             const float* __restrict__ thE, const float* __restrict__ lg1,
             const float* __restrict__ bvec, const float* __restrict__ hvec,
             float* __restrict__ out) {
    __shared__ __align__(16) float sdd[N];
    __shared__ float spart[256];
    __shared__ float part[4];
    const int b = blockIdx.x, tid = threadIdx.x;
    const int j = tid & 127, hf = tid >> 7;

    // ---- prologue: y_pred = X[b,:] @ beta[:,j] (split across halves) ----
    float yp_part = 0.f;
    {
        const float* xr = X + b * N + hf * 64;
        const float* bp = beta + (hf * 64) * N + j;
#pragma unroll 8
        for (int k = 0; k < 64; k++) yp_part = fmaf(xr[k], bp[k * N], yp_part);
    }
    spart[tid] = yp_part;

    // ---- load W half-row into registers ----
    ull w[32];
    {
        const ulonglong2* wr = reinterpret_cast<const ulonglong2*>(g_W + j * N + hf * 64);
#pragma unroll
        for (int m = 0; m < 16; m++) { ulonglong2 v = wr[m]; w[2 * m] = v.x; w[2 * m + 1] = v.y; }
    }
    const float qj = g_q[j];
    const float Q1 = g_Q1;

    __syncthreads();
    const float yp = spart[j] + spart[j + 128];
    if (hf == 0) out[BATCH * N + b * N + j] = yp;   // second half of output

    const float g1v = exp10f(lg1[0]);
    const float ev  = 1.0f / (1.0f + expf(-thE[j]));
    const float pt2 = 2.0f * (ALPHA * g1v * ev);
    const float yp2 = 2.0f * yp;
    const float up1 = hvec[j];
    const float b0  = bvec[0];
    const float inv_rs  = 1.0f / (RHO + SIGMA);
    const float inv_rho = 1.0f / RHO;
    const float omr = 1.0f - RELAX;

    float x1 = 0.f, x2 = 0.f;
    float z1 = 0.f, z2 = 0.f, z3 = 0.f;
    float y1 = 0.f, y2 = 0.f, y3 = 0.f;
    float z0 = 0.f, y0 = 0.f;

    // FIX (R2 bug): each half covers 64 floats = 16 ulonglong2 -> offset hf*16 (was hf*8)
    const ulonglong2* dds = reinterpret_cast<const ulonglong2*>(sdd) + hf * 16;

    for (int it = 0; it < NITERS; it++) {
        float wa = RHO * z1 - y1;
        float wb = RHO * z2 - y2;
        float wc = RHO * z3 - y3;
        float c2 = 2.0f * (RHO * z0 - y0);
        float ddl = SIGMA * (x1 - x2) + yp2 - 2.0f * wa - wb + wc;
        float s   = SIGMA * (x1 + x2) - pt2 - wb - wc;
        if (hf == 0) sdd[j] = ddl;
        __syncthreads();

        // reduction of q^T dd_local (warps 0-3) — overlaps matvec issue
        if (hf == 0) {
            float r = qj * ddl;
#pragma unroll
            for (int m = 16; m; m >>= 1) r += __shfl_xor_sync(0xffffffffu, r, m);
            if ((tid & 31) == 0) part[tid >> 5] = r;
        }

        // half-row matvec: 16 LDS.128 (broadcast) + 32 f32x2 FMA
        ull a0 = 0ull, a1 = 0ull, a2 = 0ull, a3 = 0ull;
#pragma unroll
        for (int m = 0; m < 8; m++) {
            ulonglong2 d0 = dds[2 * m];
            ulonglong2 d1 = dds[2 * m + 1];
            a0 = fma2(w[4 * m + 0], d0.x, a0);
            a1 = fma2(w[4 * m + 1], d0.y, a1);
            a2 = fma2(w[4 * m + 2], d1.x, a2);
            a3 = fma2(w[4 * m + 3], d1.y, a3);
        }
        F2U acc; acc.u = add2(add2(a0, a1), add2(a2, a3));
        spart[tid] = acc.f.x + acc.f.y;
        __syncthreads();

        float t   = (spart[j] + spart[j + 128]) + c2 * qj;
        float zs  = (part[0] + part[1]) + (part[2] + part[3]);
        float zt0 = zs + c2 * Q1;

        float su  = s * inv_rs;
        float xt1 = 0.5f * (su + t);
        float xt2 = 0.5f * (su - t);
        x1 = RELAX * xt1 + omr * x1;
        x2 = RELAX * xt2 + omr * x2;

        // equality row: clip(..., b0, b0) == b0 always
        float zr0 = RELAX * zt0 + omr * z0;
        y0 += RHO * (zr0 - b0); z0 = b0;

        float zr1 = RELAX * (-t) + omr * z1;
        float zn1 = fminf(zr1 + y1 * inv_rho, up1);
        y1 += RHO * (zr1 - zn1); z1 = zn1;

        float zr2 = RELAX * (-xt1) + omr * z2;
        float zn2 = fminf(zr2 + y2 * inv_rho, 0.0f);
        y2 += RHO * (zr2 - zn2); z2 = zn2;

        float zr3 = RELAX * (-xt2) + omr * z3;
        float zn3 = fminf(zr3 + y3 * inv_rho, 0.0f);
        y3 += RHO * (zr3 - zn3); z3 = zn3;
    }

    if (hf == 0) out[b * N + j] = x1 - x2;
}

// ---------------- launcher ----------------
extern "C" void kernel_launch(void* const* d_in, const int* in_sizes, int n_in,
                              void* d_out, int out_size) {
    const float* X    = (const float*)d_in[0];
    const float* V    = (const float*)d_in[1];
    const float* beta = (const float*)d_in[2];
    const float* thE  = (const float*)d_in[3];
    const float* thD  = (const float*)d_in[4];
    const float* lg1  = (const float*)d_in[5];
    const float* lg2  = (const float*)d_in[6];
    const float* bvec = (const float*)d_in[8];
    const float* hvec = (const float*)d_in[10];
    float* out = (float*)d_out;

    invert_kernel<<<1, N>>>(V, thD, lg2);
    solve_kernel<<<BATCH, 256>>>(X, beta, thE, lg1, bvec, hvec, out);
}

// round 4
// speedup vs baseline: 1.8396x; 1.2226x over previous
#include <cuda_runtime.h>

#define N 128
#define BATCH 32
#define NITERS 500
#define RHO 0.1f
#define SIGMA 1e-6f
#define RELAX 1.6f
#define ALPHA 0.5f
#define DELTA 10.0f

typedef unsigned long long ull;

// ---------------- device scratch ----------------
__device__ float g_W[N * N];   // (2Q + 2*rho*J + (3*rho+sigma)I)^{-1}
__device__ float g_q[N];       // q = W @ 1  (row sums; W symmetric)
__device__ float g_Q1;         // 1^T W 1

// ---------------- packed f32x2 helpers ----------------
union F2U { ull u; float2 f; };
__device__ __forceinline__ ull pack2(float x, float y) { F2U u; u.f = make_float2(x, y); return u.u; }
__device__ __forceinline__ ull fma2(ull a, ull b, ull c) {
    ull d; asm("fma.rn.f32x2 %0, %1, %2, %3;" : "=l"(d) : "l"(a), "l"(b), "l"(c)); return d;
}
__device__ __forceinline__ ull add2(ull a, ull b) {
    ull d; asm("add.rn.f32x2 %0, %1, %2;" : "=l"(d) : "l"(a), "l"(b)); return d;
}
__device__ __forceinline__ ull mul2(ull a, ull b) {
    ull d; asm("mul.rn.f32x2 %0, %1, %2;" : "=l"(d) : "l"(a), "l"(b)); return d;
}

// ---------------- P1: register-resident Gauss-Jordan, 256 threads, half-rows ----
// warp w, lane l: row = w*16 + (l&15), half hf = l>>4 (32 ull = 64 floats).
// Per pivot: 2-lane vectorized export (16 STS.128), 1 barrier, 32 FMA2 update,
// f exchanged between half-threads via shfl.
__global__ void __launch_bounds__(256, 1)
invert_kernel(const float* __restrict__ V, const float* __restrict__ thD,
              const float* __restrict__ lg2) {
    __shared__ __align__(16) ull rowbuf[2][64];
    __shared__ float red8[8];
    const int tid = threadIdx.x;
    const int w = tid >> 5, l = tid & 31;
    const int row = w * 16 + (l & 15);
    const int hf = l >> 4;

    const float g2 = exp10f(lg2[0]);
    const float sg = 1.0f / (1.0f + expf(-thD[row]));
    const float dg = 2.0f * (1.0f - ALPHA) * g2 * sg * sg + 3.0f * RHO + SIGMA;

    ull rr[32];
    {
        const float2* vrow = reinterpret_cast<const float2*>(V + row * N + hf * 64);
#pragma unroll
        for (int m = 0; m < 32; m++) {
            float2 v = vrow[m];
            float a = fmaf(2.0f * DELTA, v.x, 2.0f * RHO);
            float c = fmaf(2.0f * DELTA, v.y, 2.0f * RHO);
            int gc = hf * 64 + 2 * m;
            if (gc == row)     a += dg;
            if (gc + 1 == row) c += dg;
            rr[m] = pack2(a, c);
        }
    }

#pragma unroll
    for (int k = 0; k < N; k++) {
        ulonglong2* buf2 = reinterpret_cast<ulonglong2*>(rowbuf[k & 1]);
        if (row == k) {
#pragma unroll
            for (int m = 0; m < 16; m++)
                buf2[hf * 16 + m] = make_ulonglong2(rr[2 * m], rr[2 * m + 1]);
        }
        __syncthreads();
        const float* bf = reinterpret_cast<const float*>(rowbuf[k & 1]);
        const float d = 1.0f / bf[k];
        // extract f = element k of own row (owner half), exchange to partner via shfl
        const int mm = (k & 63) >> 1;
        F2U u; u.u = rr[mm];
        float fown = (k & 1) ? u.f.y : u.f.x;
        float f = __shfl_sync(0xffffffffu, fown, (l & 15) | ((k >> 6) << 4));
        const ull* bh = rowbuf[k & 1] + hf * 32;
        if (row == k) {
            ull d2 = pack2(d, d);
#pragma unroll
            for (int m = 0; m < 32; m++) rr[m] = mul2(rr[m], d2);
            if (hf == (k >> 6)) {
                F2U t; t.u = rr[mm];
                if (k & 1) t.f.y = d; else t.f.x = d;
                rr[mm] = t.u;
            }
        } else {
            float fd = f * d;
            ull nf2 = pack2(-fd, -fd);
#pragma unroll
            for (int m = 0; m < 32; m++) rr[m] = fma2(nf2, bh[m], rr[m]);
            if (hf == (k >> 6)) {
                F2U t; t.u = rr[mm];
                if (k & 1) t.f.y = -fd; else t.f.x = -fd;
                rr[mm] = t.u;
            }
        }
    }

    // q = row sums, Q1 = total sum
    ull s0 = 0, s1 = 0, s2 = 0, s3 = 0;
#pragma unroll
    for (int m = 0; m < 32; m += 4) {
        s0 = add2(s0, rr[m]); s1 = add2(s1, rr[m + 1]);
        s2 = add2(s2, rr[m + 2]); s3 = add2(s3, rr[m + 3]);
    }
    F2U ts; ts.u = add2(add2(s0, s1), add2(s2, s3));
    float qh = ts.f.x + ts.f.y;
    float qs = qh + __shfl_xor_sync(0xffffffffu, qh, 16);
    if (hf == 0) g_q[row] = qs;
    float r = qs;
#pragma unroll
    for (int m = 8; m; m >>= 1) r += __shfl_xor_sync(0xffffffffu, r, m);
    if (l == 0) red8[w] = r;
    __syncthreads();
    if (tid == 0) {
        float t = 0.f;
#pragma unroll
        for (int i = 0; i < 8; i++) t += red8[i];
        g_Q1 = t;
    }

    ulonglong2* wout = reinterpret_cast<ulonglong2*>(g_W + row * N + hf * 64);
#pragma unroll
    for (int m = 0; m < 16; m++)
        wout[m] = make_ulonglong2(rr[2 * m], rr[2 * m + 1]);
}

// ---------------- P2: persistent per-batch ADMM, 288 threads ----------------
// Warps 0-7: row j = w*16+(l&15), half hf = l>>4; cross-half sum via shfl_xor(16).
// Warp 8: scalar (equality) row — reduces q^T ddl, maintains (z0,y0), publishes
// c2 = 2*(rho*z0 - y0) via double buffer. ONE __syncthreads per iteration;
// sdd and c2 double-buffered so write(it+1) never races read(it).
__global__ void __launch_bounds__(288, 1)
solve_kernel(const float* __restrict__ X, const float* __restrict__ beta,
             const float* __restrict__ thE, const float* __restrict__ lg1,
             const float* __restrict__ bvec, const float* __restrict__ hvec,
             float* __restrict__ out) {
    __shared__ __align__(16) float sdd[2][N];
    __shared__ float c2buf[2];
    __shared__ float sx[N];
    const int b = blockIdx.x, tid = threadIdx.x;
    const int w = tid >> 5, l = tid & 31;
    const bool rowt = (w < 8);
    const int j = rowt ? (w * 16 + (l & 15)) : 0;
    const int hf = l >> 4;

    if (tid == 0) { c2buf[0] = 0.f; c2buf[1] = 0.f; }
    if (tid < N) sx[tid] = X[b * N + tid];
    __syncthreads();

    const float b0 = bvec[0];
    const float inv_rs  = 1.0f / (RHO + SIGMA);
    const float inv_rho = 1.0f / RHO;
    const float omr = 1.0f - RELAX;

    ull wreg[32];
    float qj = 0.f, Q1 = 0.f, yp2 = 0.f, pt2 = 0.f, up1 = 0.f;
    float4 qv = make_float4(0.f, 0.f, 0.f, 0.f);

    if (rowt) {
        // y_pred half-dot (coalesced beta columns), full via shfl
        float acc = 0.f;
        const float* bp = beta + (hf * 64) * N + j;
        const float* xp = sx + hf * 64;
#pragma unroll 8
        for (int k = 0; k < 64; k++) acc = fmaf(xp[k], bp[k * N], acc);
        float yp = acc + __shfl_xor_sync(0xffffffffu, acc, 16);
        if (hf == 0) out[BATCH * N + b * N + j] = yp;
        yp2 = 2.0f * yp;
        const float g1v = exp10f(lg1[0]);
        const float ev  = 1.0f / (1.0f + expf(-thE[j]));
        pt2 = 2.0f * (ALPHA * g1v * ev);
        up1 = hvec[j];
        qj  = g_q[j];
        const ulonglong2* wr = reinterpret_cast<const ulonglong2*>(g_W + j * N + hf * 64);
#pragma unroll
        for (int m = 0; m < 16; m++) {
            ulonglong2 v = wr[m]; wreg[2 * m] = v.x; wreg[2 * m + 1] = v.y;
        }
    } else {
        qv = *reinterpret_cast<const float4*>(g_q + 4 * l);
        Q1 = g_Q1;
    }

    float x1 = 0.f, x2 = 0.f;
    float z1 = 0.f, z2 = 0.f, z3 = 0.f;
    float y1 = 0.f, y2 = 0.f, y3 = 0.f;
    float z0 = 0.f, y0 = 0.f;   // warp-8 scalar row state

#pragma unroll 2
    for (int it = 0; it < NITERS; it++) {
        const int p = it & 1;
        float s = 0.f;
        if (rowt) {
            float wa = RHO * z1 - y1;
            float wb = RHO * z2 - y2;
            float wc = RHO * z3 - y3;
            float ddl = SIGMA * (x1 - x2) + yp2 - 2.0f * wa - wb + wc;
            s = SIGMA * (x1 + x2) - pt2 - wb - wc;
            if (hf == 0) sdd[p][j] = ddl;
        }
        __syncthreads();

        if (rowt) {
            const ulonglong2* dds = reinterpret_cast<const ulonglong2*>(sdd[p]) + hf * 16;
            ull a0 = 0ull, a1 = 0ull, a2 = 0ull, a3 = 0ull;
#pragma unroll
            for (int m = 0; m < 4; m++) {
                ulonglong2 d0 = dds[4 * m];
                ulonglong2 d1 = dds[4 * m + 1];
                ulonglong2 d2 = dds[4 * m + 2];
                ulonglong2 d3 = dds[4 * m + 3];
                a0 = fma2(wreg[8 * m + 0], d0.x, a0);
                a1 = fma2(wreg[8 * m + 1], d0.y, a1);
                a2 = fma2(wreg[8 * m + 2], d1.x, a2);
                a3 = fma2(wreg[8 * m + 3], d1.y, a3);
                a0 = fma2(wreg[8 * m + 4], d2.x, a0);
                a1 = fma2(wreg[8 * m + 5], d2.y, a1);
                a2 = fma2(wreg[8 * m + 6], d3.x, a2);
                a3 = fma2(wreg[8 * m + 7], d3.y, a3);
            }
            F2U acc; acc.u = add2(add2(a0, a1), add2(a2, a3));
            float th = acc.f.x + acc.f.y;
            float c2 = c2buf[p];
            float t = (th + __shfl_xor_sync(0xffffffffu, th, 16)) + c2 * qj;

            float su  = s * inv_rs;
            float xt1 = 0.5f * (su + t);
            float xt2 = 0.5f * (su - t);
            x1 = RELAX * xt1 + omr * x1;
            x2 = RELAX * xt2 + omr * x2;

            float zr1 = RELAX * (-t) + omr * z1;
            float zn1 = fminf(zr1 + y1 * inv_rho, up1);
            y1 += RHO * (zr1 - zn1); z1 = zn1;

            float zr2 = RELAX * (-xt1) + omr * z2;
            float zn2 = fminf(zr2 + y2 * inv_rho, 0.0f);
            y2 += RHO * (zr2 - zn2); z2 = zn2;

            float zr3 = RELAX * (-xt2) + omr * z3;
            float zn3 = fminf(zr3 + y3 * inv_rho, 0.0f);
            y3 += RHO * (zr3 - zn3); z3 = zn3;
        } else {
            // scalar equality row: zt0 = q^T ddl + c2 * Q1
            float4 d4 = reinterpret_cast<const float4*>(sdd[p])[l];
            float r = qv.x * d4.x + qv.y * d4.y + qv.z * d4.z + qv.w * d4.w;
#pragma unroll
            for (int m = 16; m; m >>= 1) r += __shfl_xor_sync(0xffffffffu, r, m);
            float c2 = c2buf[p];
            float zt0 = r + c2 * Q1;
            float zr0 = RELAX * zt0 + omr * z0;
            y0 += RHO * (zr0 - b0); z0 = b0;   // clip(.., b0, b0) == b0
            if (l == 0) c2buf[p ^ 1] = 2.0f * (RHO * z0 - y0);
        }
    }

    if (rowt && hf == 0) out[b * N + j] = x1 - x2;
}

// ---------------- launcher ----------------
extern "C" void kernel_launch(void* const* d_in, const int* in_sizes, int n_in,
                              void* d_out, int out_size) {
    const float* X    = (const float*)d_in[0];
    const float* V    = (const float*)d_in[1];
    const float* beta = (const float*)d_in[2];
    const float* thE  = (const float*)d_in[3];
    const float* thD  = (const float*)d_in[4];
    const float* lg1  = (const float*)d_in[5];
    const float* lg2  = (const float*)d_in[6];
    const float* bvec = (const float*)d_in[8];
    const float* hvec = (const float*)d_in[10];
    float* out = (float*)d_out;

    invert_kernel<<<1, 256>>>(V, thD, lg2);
    solve_kernel<<<BATCH, 288>>>(X, beta, thE, lg1, bvec, hvec, out);
}